// round 15
// baseline (speedup 1.0000x reference)
#include <cuda_runtime.h>
#include <math.h>

#define TT 300   // time steps

// ---------------- scratch (static device globals: allowed scratch) -------------
__device__ float g_buf0[27100000];
__device__ float g_buf1[27100000];
__device__ float g_buf2[27100000];

// ---------------- psp: causal FIR, K=100, Eigen AVX2 swapped-gebp shape --------
// XLA-CPU RowMajor => conv contraction has M=O=1; every output computed by the
// swapped 1x4 micro-kernel with Packet8f:
//   lane l (0..7): chain c_l = serial fma over m=0..11 of K[8m+l]*xpad[t+8m+l]
//   tail (k=96..99): half-packet products ch_l = K[96+l]*xpad[t+96+l]
//   fold: f_l = (c_l + c_{l+4}) + ch_l          (predux_half_dowto4 + padd)
//   combine: y = (f0+f1) + (f2+f3)              (ptranspose path)
// K[j] = eps[99-j] (reverse folded into the constant); 99 zeros left padding
// participate as exact no-ops.
__global__ void psp_kernel(const float* __restrict__ x, float* __restrict__ y) {
    __shared__ float sx[304];
    __shared__ float se[104];
    long long r = blockIdx.x;
    const float* xr = x + r * TT;
    int tid = threadIdx.x;
    for (int i = tid; i < TT; i += blockDim.x) sx[i] = xr[i];
    for (int i = tid; i < 104; i += blockDim.x) {
        float v = 0.f;
        if (i >= 1 && i < 100) {
            float kf = (float)i;
            float k10 = __fdiv_rn(kf, 10.0f);
            float arg = __fsub_rn(1.0f, k10);
            float e = (float)exp((double)arg);     // correctly-rounded exp of fp32 arg
            v = __fmul_rn(k10, e);
        }
        se[i] = v;
    }
    __syncthreads();
    if (tid < 100) {
        int t0 = tid * 3;
        #pragma unroll
        for (int q = 0; q < 3; ++q) {
            int t = t0 + q;
            float c[8];
            #pragma unroll
            for (int l = 0; l < 8; ++l) c[l] = 0.f;
            #pragma unroll 3
            for (int m = 0; m < 12; ++m) {
                #pragma unroll
                for (int l = 0; l < 8; ++l) {
                    int j = 8 * m + l;
                    int xi = t - 99 + j;
                    float xv = (xi >= 0) ? sx[xi] : 0.f;
                    c[l] = fmaf(se[99 - j], xv, c[l]);   // Eigen pmadd = FMA
                }
            }
            float f[4];
            #pragma unroll
            for (int l = 0; l < 4; ++l) {
                int xi = t - 3 + l;                      // j = 96+l
                float xv = (xi >= 0) ? sx[xi] : 0.f;
                float ch = __fmul_rn(se[3 - l], xv);     // fma into zero acc = exact product
                f[l] = __fadd_rn(__fadd_rn(c[l], c[l + 4]), ch);
            }
            y[r * TT + t] = __fadd_rn(__fadd_rn(f[0], f[1]), __fadd_rn(f[2], f[3]));
        }
    }
}

// ---------------- conv (1 x 3, stride 2 along W) + spike -----------------------
template <int CIN, int COUT, int PAD>
__global__ void conv_spike_kernel(const float* __restrict__ X,
                                  const float* __restrict__ Wt,
                                  float* __restrict__ Y,
                                  int Win, int Wout) {
    extern __shared__ float sm[];
    const int CK = CIN * 3;
    float* sW = sm;             // COUT*CK
    float* sX = sm + COUT * CK; // CK*TT
    int wo = blockIdx.x, n = blockIdx.y;
    int tid = threadIdx.x; int NT = blockDim.x;

    for (int i = tid; i < COUT * CK; i += NT) sW[i] = Wt[i];
    for (int i = tid; i < CK * TT; i += NT) {
        int idx = i / TT, t = i - idx * TT;
        int ci = idx / 3, kw = idx - ci * 3;
        int wi = wo * 2 - PAD + kw;
        float v = 0.f;
        if (wi >= 0 && wi < Win)
            v = X[((long long)(n * CIN + ci) * Win + wi) * TT + t];
        sX[i] = v;
    }
    __syncthreads();

    const int TCOG = COUT / 4;
    const int TASKS = TCOG * 75;    // 75 t-groups of 4
    for (int task = tid; task < TASKS; task += NT) {
        int cog = task / 75, tg = task - cog * 75;
        int co0 = cog * 4, t0 = tg * 4;
        float acc[4][4];
        #pragma unroll
        for (int j = 0; j < 4; ++j)
            acc[j][0] = acc[j][1] = acc[j][2] = acc[j][3] = 0.f;
        for (int ck = 0; ck < CK; ++ck) {       // serial ascending (flip-inert)
            float4 xv = *(const float4*)&sX[ck * TT + t0];
            #pragma unroll
            for (int j = 0; j < 4; ++j) {
                float wv = sW[(co0 + j) * CK + ck];
                acc[j][0] = fmaf(wv, xv.x, acc[j][0]);
                acc[j][1] = fmaf(wv, xv.y, acc[j][1]);
                acc[j][2] = fmaf(wv, xv.z, acc[j][2]);
                acc[j][3] = fmaf(wv, xv.w, acc[j][3]);
            }
        }
        #pragma unroll
        for (int j = 0; j < 4; ++j) {
            float* yp = Y + ((long long)(n * COUT + co0 + j) * Wout + wo) * TT + t0;
            #pragma unroll
            for (int q = 0; q < 4; ++q)
                yp[q] = (acc[j][q] >= 1.0f) ? 1.0f : 0.0f;
        }
    }
}

// ---------------- per-channel fractional delay (non-fma) -----------------------
__global__ void delay_kernel(const float* __restrict__ X, float* __restrict__ Y,
                             const float* __restrict__ D, int C, int Wd) {
    long long r = blockIdx.x;                 // row over (n, c, w)
    int c = (int)((r / Wd) % C);
    float d = D[c];
    float tf = floorf(d);
    int tfi = (int)tf;
    float fr = __fsub_rn(d, tf);
    float one_minus_fr = __fsub_rn(1.0f, fr);
    const float* xr = X + r * TT;
    float* yr = Y + r * TT;
    for (int t = threadIdx.x; t < TT; t += blockDim.x) {
        int i0 = t - tfi, i1 = i0 - 1;
        float g0 = (i0 >= 0) ? xr[i0] : 0.f;
        float g1 = (i1 >= 0) ? xr[i1] : 0.f;
        yr[t] = __fadd_rn(__fmul_rn(one_minus_fr, g0), __fmul_rn(fr, g1));
    }
}

// ---------------- dense1 (512 x 2816) per time step + spike --------------------
__global__ void dense1_spike_kernel(const float* __restrict__ A,
                                    const float* __restrict__ Wt,
                                    float* __restrict__ Y) {
    __shared__ float sA[32 * 64];
    __shared__ float sW[64 * 33];
    int tb = blockIdx.x * 64, ob = blockIdx.y * 64, n = blockIdx.z;
    int tid = threadIdx.x;                 // 256
    int to = tid & 15, tg = tid >> 4;
    int o0 = to * 4, t0 = tg * 4;
    float acc[4][4];
    #pragma unroll
    for (int j = 0; j < 4; ++j)
        acc[j][0] = acc[j][1] = acc[j][2] = acc[j][3] = 0.f;
    const float* An = A + (long long)n * 2816 * TT;

    for (int k0 = 0; k0 < 2816; k0 += 32) {
        for (int i = tid; i < 2048; i += 256) {
            int k = i >> 6, t = i & 63;
            int tgl = tb + t;
            sA[k * 64 + t] = (tgl < TT) ? An[(long long)(k0 + k) * TT + tgl] : 0.f;
        }
        for (int i = tid; i < 2048; i += 256) {
            int o = i >> 5, k = i & 31;
            sW[o * 33 + k] = Wt[(long long)(ob + o) * 2816 + k0 + k];
        }
        __syncthreads();
        #pragma unroll 8
        for (int k = 0; k < 32; ++k) {
            float4 av = *(const float4*)&sA[k * 64 + t0];
            float w0 = sW[(o0 + 0) * 33 + k];
            float w1 = sW[(o0 + 1) * 33 + k];
            float w2 = sW[(o0 + 2) * 33 + k];
            float w3 = sW[(o0 + 3) * 33 + k];
            acc[0][0] = fmaf(w0, av.x, acc[0][0]); acc[0][1] = fmaf(w0, av.y, acc[0][1]);
            acc[0][2] = fmaf(w0, av.z, acc[0][2]); acc[0][3] = fmaf(w0, av.w, acc[0][3]);
            acc[1][0] = fmaf(w1, av.x, acc[1][0]); acc[1][1] = fmaf(w1, av.y, acc[1][1]);
            acc[1][2] = fmaf(w1, av.z, acc[1][2]); acc[1][3] = fmaf(w1, av.w, acc[1][3]);
            acc[2][0] = fmaf(w2, av.x, acc[2][0]); acc[2][1] = fmaf(w2, av.y, acc[2][1]);
            acc[2][2] = fmaf(w2, av.z, acc[2][2]); acc[2][3] = fmaf(w2, av.w, acc[2][3]);
            acc[3][0] = fmaf(w3, av.x, acc[3][0]); acc[3][1] = fmaf(w3, av.y, acc[3][1]);
            acc[3][2] = fmaf(w3, av.z, acc[3][2]); acc[3][3] = fmaf(w3, av.w, acc[3][3]);
        }
        __syncthreads();
    }
    #pragma unroll
    for (int j = 0; j < 4; ++j) {
        #pragma unroll
        for (int q = 0; q < 4; ++q) {
            int t = tb + t0 + q;
            if (t < TT)
                Y[((long long)(n * 512 + ob + o0 + j)) * TT + t] =
                    (acc[j][q] >= 1.0f) ? 1.0f : 0.0f;
        }
    }
}

// ---------------- dense2 (35 x 512) + spike -> d_out ---------------------------
__global__ void dense2_spike_kernel(const float* __restrict__ A,
                                    const float* __restrict__ Wt,
                                    float* __restrict__ Y) {
    int o = blockIdx.x, n = blockIdx.y;
    __shared__ float sw[512];
    for (int i = threadIdx.x; i < 512; i += blockDim.x) sw[i] = Wt[o * 512 + i];
    __syncthreads();
    const float* An = A + (long long)n * 512 * TT;
    for (int t = threadIdx.x; t < TT; t += blockDim.x) {
        float acc = 0.f;
        for (int f = 0; f < 512; ++f)
            acc = fmaf(sw[f], An[(long long)f * TT + t], acc);
        Y[((long long)(n * 35 + o)) * TT + t] = (acc >= 1.0f) ? 1.0f : 0.0f;
    }
}

// ---------------- launch sequence ----------------------------------------------
extern "C" void kernel_launch(void* const* d_in, const int* in_sizes, int n_in,
                              void* d_out, int out_size) {
    (void)in_sizes; (void)n_in; (void)out_size;
    const float* spike = (const float*)d_in[0];
    const float* W1 = (const float*)d_in[1];
    const float* W2 = (const float*)d_in[2];
    const float* W3 = (const float*)d_in[3];
    const float* W4 = (const float*)d_in[4];
    const float* Wf1 = (const float*)d_in[5];
    const float* Wf2 = (const float*)d_in[6];
    const float* d1 = (const float*)d_in[7];
    const float* d2 = (const float*)d_in[8];
    const float* d3 = (const float*)d_in[9];
    const float* d4 = (const float*)d_in[10];
    const float* d5 = (const float*)d_in[11];

    float *b0, *b1, *b2;
    cudaGetSymbolAddress((void**)&b0, g_buf0);
    cudaGetSymbolAddress((void**)&b1, g_buf1);
    cudaGetSymbolAddress((void**)&b2, g_buf2);

    cudaFuncSetAttribute(conv_spike_kernel<16, 32, 1>,
                         cudaFuncAttributeMaxDynamicSharedMemorySize, (1536 + 48 * TT) * 4);
    cudaFuncSetAttribute(conv_spike_kernel<32, 64, 1>,
                         cudaFuncAttributeMaxDynamicSharedMemorySize, (6144 + 96 * TT) * 4);

    // layer 1: (32,1,691) -> (32,8,345)
    psp_kernel<<<32 * 691, 128>>>(spike, b0);
    conv_spike_kernel<1, 8, 0><<<dim3(345, 32), 128, (24 + 3 * TT) * 4>>>(b0, W1, b1, 691, 345);
    delay_kernel<<<32 * 8 * 345, 128>>>(b1, b2, d1, 8, 345);

    // layer 2: -> (32,16,173)
    psp_kernel<<<32 * 8 * 345, 128>>>(b2, b0);
    conv_spike_kernel<8, 16, 1><<<dim3(173, 32), 128, (384 + 24 * TT) * 4>>>(b0, W2, b1, 345, 173);
    delay_kernel<<<32 * 16 * 173, 128>>>(b1, b2, d2, 16, 173);

    // layer 3: -> (32,32,87)
    psp_kernel<<<32 * 16 * 173, 128>>>(b2, b0);
    conv_spike_kernel<16, 32, 1><<<dim3(87, 32), 256, (1536 + 48 * TT) * 4>>>(b0, W3, b1, 173, 87);
    delay_kernel<<<32 * 32 * 87, 128>>>(b1, b2, d3, 32, 87);

    // layer 4: -> (32,64,44)
    psp_kernel<<<32 * 32 * 87, 128>>>(b2, b0);
    conv_spike_kernel<32, 64, 1><<<dim3(44, 32), 256, (6144 + 96 * TT) * 4>>>(b0, W4, b1, 87, 44);
    delay_kernel<<<32 * 64 * 44, 128>>>(b1, b2, d4, 64, 44);

    // dense 1: features f = c*44+w = 2816 (layout already matches)
    psp_kernel<<<32 * 2816, 128>>>(b2, b0);
    dense1_spike_kernel<<<dim3(5, 8, 32), 256>>>(b0, Wf1, b1);
    delay_kernel<<<32 * 512, 128>>>(b1, b2, d5, 512, 1);

    // dense 2 -> output (32,35,300)
    psp_kernel<<<32 * 512, 128>>>(b2, b0);
    dense2_spike_kernel<<<dim3(35, 32), 128>>>(b0, Wf2, (float*)d_out);
}

// round 16
// speedup vs baseline: 1.4961x; 1.4961x over previous
#include <cuda_runtime.h>
#include <math.h>

#define TT 300   // time steps

// ---------------- scratch (static device globals: allowed scratch) -------------
__device__ float g_buf0[27100000];
__device__ float g_buf1[27100000];
__device__ float g_buf2[27100000];
__device__ float g_K[104];          // flipped psp kernel: K[j] = eps[99-j]

// ---------------- init: compute flipped eps table once --------------------------
// Same fp ops as before (fp32 stepwise + correctly-rounded exp) => same bits.
__global__ void init_kernel() {
    int j = threadIdx.x;
    if (j < 104) {
        float v = 0.f;
        int i = 99 - j;                       // eps index
        if (i >= 1 && i < 100) {
            float kf = (float)i;
            float k10 = __fdiv_rn(kf, 10.0f);
            float arg = __fsub_rn(1.0f, k10);
            float e = (float)exp((double)arg);
            v = __fmul_rn(k10, e);
        }
        g_K[j] = v;
    }
}

// ---------------- psp: causal FIR, K=100, Eigen AVX2 swapped-gebp shape --------
// Bit-exact shape (verified rel_err==0):
//   lane l: c_l = serial fma over m=0..11 of K[8m+l]*xpad[t+8m+l]
//   tail:   ch_l = K[96+l]*xpad[t+96+l]  (l=0..3)
//   fold:   f_l = (c_l + c_{l+4}) + ch_l ;  y = (f0+f1)+(f2+f3)
// Optimization only: padded smem input (predicate-free, exact zeros), K table
// hoisted to a global computed once, 3 outputs interleaved so K is read once
// per tap and x reads CSE across l/q.
__global__ void psp_kernel(const float* __restrict__ x, float* __restrict__ y) {
    __shared__ float sxp[404];      // 99 zeros + 300 row + pad
    __shared__ float sK[104];
    long long r = blockIdx.x;
    const float* xr = x + r * TT;
    int tid = threadIdx.x;
    for (int i = tid; i < 99; i += blockDim.x) sxp[i] = 0.f;
    for (int i = tid; i < TT; i += blockDim.x) sxp[99 + i] = xr[i];
    for (int i = tid; i < 104; i += blockDim.x) sK[i] = g_K[i];
    __syncthreads();
    if (tid < 100) {
        int t0 = tid * 3;
        const float* xb = sxp + t0;           // xb[q + j] = xpad[t0+q+j]
        float c0[8], c1[8], c2[8];
        #pragma unroll
        for (int l = 0; l < 8; ++l) { c0[l] = c1[l] = c2[l] = 0.f; }
        #pragma unroll
        for (int m = 0; m < 12; ++m) {
            #pragma unroll
            for (int l = 0; l < 8; ++l) {
                int j = 8 * m + l;
                float kj = sK[j];             // one K read per tap (broadcast)
                float xa = xb[j];
                float xbv = xb[j + 1];
                float xc = xb[j + 2];
                c0[l] = fmaf(kj, xa,  c0[l]);
                c1[l] = fmaf(kj, xbv, c1[l]);
                c2[l] = fmaf(kj, xc,  c2[l]);
            }
        }
        float* yr = y + r * TT + t0;
        #pragma unroll
        for (int q = 0; q < 3; ++q) {
            float* cc = (q == 0) ? c0 : (q == 1) ? c1 : c2;
            float f[4];
            #pragma unroll
            for (int l = 0; l < 4; ++l) {
                float ch = __fmul_rn(sK[96 + l], xb[96 + l + q]);
                f[l] = __fadd_rn(__fadd_rn(cc[l], cc[l + 4]), ch);
            }
            yr[q] = __fadd_rn(__fadd_rn(f[0], f[1]), __fadd_rn(f[2], f[3]));
        }
    }
}

// ---------------- conv (1 x 3, stride 2 along W) + spike -----------------------
template <int CIN, int COUT, int PAD>
__global__ void conv_spike_kernel(const float* __restrict__ X,
                                  const float* __restrict__ Wt,
                                  float* __restrict__ Y,
                                  int Win, int Wout) {
    extern __shared__ float sm[];
    const int CK = CIN * 3;
    float* sW = sm;             // COUT*CK
    float* sX = sm + COUT * CK; // CK*TT
    int wo = blockIdx.x, n = blockIdx.y;
    int tid = threadIdx.x; int NT = blockDim.x;

    for (int i = tid; i < COUT * CK; i += NT) sW[i] = Wt[i];
    for (int i = tid; i < CK * TT; i += NT) {
        int idx = i / TT, t = i - idx * TT;
        int ci = idx / 3, kw = idx - ci * 3;
        int wi = wo * 2 - PAD + kw;
        float v = 0.f;
        if (wi >= 0 && wi < Win)
            v = X[((long long)(n * CIN + ci) * Win + wi) * TT + t];
        sX[i] = v;
    }
    __syncthreads();

    const int TCOG = COUT / 4;
    const int TASKS = TCOG * 75;    // 75 t-groups of 4
    for (int task = tid; task < TASKS; task += NT) {
        int cog = task / 75, tg = task - cog * 75;
        int co0 = cog * 4, t0 = tg * 4;
        float acc[4][4];
        #pragma unroll
        for (int j = 0; j < 4; ++j)
            acc[j][0] = acc[j][1] = acc[j][2] = acc[j][3] = 0.f;
        for (int ck = 0; ck < CK; ++ck) {
            float4 xv = *(const float4*)&sX[ck * TT + t0];
            #pragma unroll
            for (int j = 0; j < 4; ++j) {
                float wv = sW[(co0 + j) * CK + ck];
                acc[j][0] = fmaf(wv, xv.x, acc[j][0]);
                acc[j][1] = fmaf(wv, xv.y, acc[j][1]);
                acc[j][2] = fmaf(wv, xv.z, acc[j][2]);
                acc[j][3] = fmaf(wv, xv.w, acc[j][3]);
            }
        }
        #pragma unroll
        for (int j = 0; j < 4; ++j) {
            float* yp = Y + ((long long)(n * COUT + co0 + j) * Wout + wo) * TT + t0;
            #pragma unroll
            for (int q = 0; q < 4; ++q)
                yp[q] = (acc[j][q] >= 1.0f) ? 1.0f : 0.0f;
        }
    }
}

// ---------------- per-channel fractional delay (non-fma) -----------------------
__global__ void delay_kernel(const float* __restrict__ X, float* __restrict__ Y,
                             const float* __restrict__ D, int C, int Wd) {
    long long r = blockIdx.x;                 // row over (n, c, w)
    int c = (int)((r / Wd) % C);
    float d = D[c];
    float tf = floorf(d);
    int tfi = (int)tf;
    float fr = __fsub_rn(d, tf);
    float one_minus_fr = __fsub_rn(1.0f, fr);
    const float* xr = X + r * TT;
    float* yr = Y + r * TT;
    for (int t = threadIdx.x; t < TT; t += blockDim.x) {
        int i0 = t - tfi, i1 = i0 - 1;
        float g0 = (i0 >= 0) ? xr[i0] : 0.f;
        float g1 = (i1 >= 0) ? xr[i1] : 0.f;
        yr[t] = __fadd_rn(__fmul_rn(one_minus_fr, g0), __fmul_rn(fr, g1));
    }
}

// ---------------- dense1 (512 x 2816) per time step + spike --------------------
__global__ void dense1_spike_kernel(const float* __restrict__ A,
                                    const float* __restrict__ Wt,
                                    float* __restrict__ Y) {
    __shared__ float sA[32 * 64];
    __shared__ float sW[64 * 33];
    int tb = blockIdx.x * 64, ob = blockIdx.y * 64, n = blockIdx.z;
    int tid = threadIdx.x;                 // 256
    int to = tid & 15, tg = tid >> 4;
    int o0 = to * 4, t0 = tg * 4;
    float acc[4][4];
    #pragma unroll
    for (int j = 0; j < 4; ++j)
        acc[j][0] = acc[j][1] = acc[j][2] = acc[j][3] = 0.f;
    const float* An = A + (long long)n * 2816 * TT;

    for (int k0 = 0; k0 < 2816; k0 += 32) {
        for (int i = tid; i < 2048; i += 256) {
            int k = i >> 6, t = i & 63;
            int tgl = tb + t;
            sA[k * 64 + t] = (tgl < TT) ? An[(long long)(k0 + k) * TT + tgl] : 0.f;
        }
        for (int i = tid; i < 2048; i += 256) {
            int o = i >> 5, k = i & 31;
            sW[o * 33 + k] = Wt[(long long)(ob + o) * 2816 + k0 + k];
        }
        __syncthreads();
        #pragma unroll 8
        for (int k = 0; k < 32; ++k) {
            float4 av = *(const float4*)&sA[k * 64 + t0];
            float w0 = sW[(o0 + 0) * 33 + k];
            float w1 = sW[(o0 + 1) * 33 + k];
            float w2 = sW[(o0 + 2) * 33 + k];
            float w3 = sW[(o0 + 3) * 33 + k];
            acc[0][0] = fmaf(w0, av.x, acc[0][0]); acc[0][1] = fmaf(w0, av.y, acc[0][1]);
            acc[0][2] = fmaf(w0, av.z, acc[0][2]); acc[0][3] = fmaf(w0, av.w, acc[0][3]);
            acc[1][0] = fmaf(w1, av.x, acc[1][0]); acc[1][1] = fmaf(w1, av.y, acc[1][1]);
            acc[1][2] = fmaf(w1, av.z, acc[1][2]); acc[1][3] = fmaf(w1, av.w, acc[1][3]);
            acc[2][0] = fmaf(w2, av.x, acc[2][0]); acc[2][1] = fmaf(w2, av.y, acc[2][1]);
            acc[2][2] = fmaf(w2, av.z, acc[2][2]); acc[2][3] = fmaf(w2, av.w, acc[2][3]);
            acc[3][0] = fmaf(w3, av.x, acc[3][0]); acc[3][1] = fmaf(w3, av.y, acc[3][1]);
            acc[3][2] = fmaf(w3, av.z, acc[3][2]); acc[3][3] = fmaf(w3, av.w, acc[3][3]);
        }
        __syncthreads();
    }
    #pragma unroll
    for (int j = 0; j < 4; ++j) {
        #pragma unroll
        for (int q = 0; q < 4; ++q) {
            int t = tb + t0 + q;
            if (t < TT)
                Y[((long long)(n * 512 + ob + o0 + j)) * TT + t] =
                    (acc[j][q] >= 1.0f) ? 1.0f : 0.0f;
        }
    }
}

// ---------------- dense2 (35 x 512) + spike -> d_out ---------------------------
__global__ void dense2_spike_kernel(const float* __restrict__ A,
                                    const float* __restrict__ Wt,
                                    float* __restrict__ Y) {
    int o = blockIdx.x, n = blockIdx.y;
    __shared__ float sw[512];
    for (int i = threadIdx.x; i < 512; i += blockDim.x) sw[i] = Wt[o * 512 + i];
    __syncthreads();
    const float* An = A + (long long)n * 512 * TT;
    for (int t = threadIdx.x; t < TT; t += blockDim.x) {
        float acc = 0.f;
        for (int f = 0; f < 512; ++f)
            acc = fmaf(sw[f], An[(long long)f * TT + t], acc);
        Y[((long long)(n * 35 + o)) * TT + t] = (acc >= 1.0f) ? 1.0f : 0.0f;
    }
}

// ---------------- launch sequence ----------------------------------------------
extern "C" void kernel_launch(void* const* d_in, const int* in_sizes, int n_in,
                              void* d_out, int out_size) {
    (void)in_sizes; (void)n_in; (void)out_size;
    const float* spike = (const float*)d_in[0];
    const float* W1 = (const float*)d_in[1];
    const float* W2 = (const float*)d_in[2];
    const float* W3 = (const float*)d_in[3];
    const float* W4 = (const float*)d_in[4];
    const float* Wf1 = (const float*)d_in[5];
    const float* Wf2 = (const float*)d_in[6];
    const float* d1 = (const float*)d_in[7];
    const float* d2 = (const float*)d_in[8];
    const float* d3 = (const float*)d_in[9];
    const float* d4 = (const float*)d_in[10];
    const float* d5 = (const float*)d_in[11];

    float *b0, *b1, *b2;
    cudaGetSymbolAddress((void**)&b0, g_buf0);
    cudaGetSymbolAddress((void**)&b1, g_buf1);
    cudaGetSymbolAddress((void**)&b2, g_buf2);

    cudaFuncSetAttribute(conv_spike_kernel<16, 32, 1>,
                         cudaFuncAttributeMaxDynamicSharedMemorySize, (1536 + 48 * TT) * 4);
    cudaFuncSetAttribute(conv_spike_kernel<32, 64, 1>,
                         cudaFuncAttributeMaxDynamicSharedMemorySize, (6144 + 96 * TT) * 4);

    init_kernel<<<1, 128>>>();

    // layer 1: (32,1,691) -> (32,8,345)
    psp_kernel<<<32 * 691, 128>>>(spike, b0);
    conv_spike_kernel<1, 8, 0><<<dim3(345, 32), 128, (24 + 3 * TT) * 4>>>(b0, W1, b1, 691, 345);
    delay_kernel<<<32 * 8 * 345, 128>>>(b1, b2, d1, 8, 345);

    // layer 2: -> (32,16,173)
    psp_kernel<<<32 * 8 * 345, 128>>>(b2, b0);
    conv_spike_kernel<8, 16, 1><<<dim3(173, 32), 128, (384 + 24 * TT) * 4>>>(b0, W2, b1, 345, 173);
    delay_kernel<<<32 * 16 * 173, 128>>>(b1, b2, d2, 16, 173);

    // layer 3: -> (32,32,87)
    psp_kernel<<<32 * 16 * 173, 128>>>(b2, b0);
    conv_spike_kernel<16, 32, 1><<<dim3(87, 32), 256, (1536 + 48 * TT) * 4>>>(b0, W3, b1, 173, 87);
    delay_kernel<<<32 * 32 * 87, 128>>>(b1, b2, d3, 32, 87);

    // layer 4: -> (32,64,44)
    psp_kernel<<<32 * 32 * 87, 128>>>(b2, b0);
    conv_spike_kernel<32, 64, 1><<<dim3(44, 32), 256, (6144 + 96 * TT) * 4>>>(b0, W4, b1, 87, 44);
    delay_kernel<<<32 * 64 * 44, 128>>>(b1, b2, d4, 64, 44);

    // dense 1: features f = c*44+w = 2816 (layout already matches)
    psp_kernel<<<32 * 2816, 128>>>(b2, b0);
    dense1_spike_kernel<<<dim3(5, 8, 32), 256>>>(b0, Wf1, b1);
    delay_kernel<<<32 * 512, 128>>>(b1, b2, d5, 512, 1);

    // dense 2 -> output (32,35,300)
    psp_kernel<<<32 * 512, 128>>>(b2, b0);
    dense2_spike_kernel<<<dim3(35, 32), 128>>>(b0, Wf2, (float*)d_out);
}

// round 17
// speedup vs baseline: 1.6148x; 1.0794x over previous
#include <cuda_runtime.h>
#include <math.h>

#define TT 300   // time steps

// ---------------- scratch (static device globals: allowed scratch) -------------
__device__ float g_buf0[27100000];
__device__ float g_buf1[27100000];
__device__ float g_K[104];          // flipped psp kernel: K[j] = eps[99-j]

// ---------------- init: compute flipped eps table once --------------------------
__global__ void init_kernel() {
    int j = threadIdx.x;
    if (j < 104) {
        float v = 0.f;
        int i = 99 - j;                       // eps index
        if (i >= 1 && i < 100) {
            float kf = (float)i;
            float k10 = __fdiv_rn(kf, 10.0f);
            float arg = __fsub_rn(1.0f, k10);
            float e = (float)exp((double)arg);
            v = __fmul_rn(k10, e);
        }
        g_K[j] = v;
    }
}

// ---------------- psp compute core (Eigen AVX2 swapped-gebp, bit-exact) --------
// Per output t: lane l chain c_l = serial fma m=0..11 of K[8m+l]*xpad[t+8m+l];
// tail ch_l = K[96+l]*xpad[t+96+l]; fold f_l=(c_l+c_{l+4})+ch_l;
// y = (f0+f1)+(f2+f3).  4 outputs per thread (t0=4*tid) -> all float4 aligned.
__device__ __forceinline__ void psp_compute(const float* __restrict__ sxp,
                                            const float* __restrict__ sK,
                                            int tid, float* __restrict__ yr) {
    if (tid < 75) {
        int t0 = tid * 4;
        const float* xb = sxp + t0;
        float c[8][4];
        #pragma unroll
        for (int l = 0; l < 8; ++l)
            c[l][0] = c[l][1] = c[l][2] = c[l][3] = 0.f;
        #pragma unroll
        for (int m = 0; m < 12; ++m) {
            float4 k0 = *(const float4*)&sK[8 * m];
            float4 k1 = *(const float4*)&sK[8 * m + 4];
            float4 x0 = *(const float4*)&xb[8 * m];
            float4 x1 = *(const float4*)&xb[8 * m + 4];
            float4 x2 = *(const float4*)&xb[8 * m + 8];
            float kk[8] = {k0.x, k0.y, k0.z, k0.w, k1.x, k1.y, k1.z, k1.w};
            float xs[12] = {x0.x, x0.y, x0.z, x0.w, x1.x, x1.y, x1.z, x1.w,
                            x2.x, x2.y, x2.z, x2.w};
            #pragma unroll
            for (int l = 0; l < 8; ++l) {
                #pragma unroll
                for (int q = 0; q < 4; ++q)
                    c[l][q] = fmaf(kk[l], xs[l + q], c[l][q]);
            }
        }
        #pragma unroll
        for (int q = 0; q < 4; ++q) {
            float f[4];
            #pragma unroll
            for (int l = 0; l < 4; ++l) {
                float ch = __fmul_rn(sK[96 + l], xb[96 + l + q]);
                f[l] = __fadd_rn(__fadd_rn(c[l][q], c[l + 4][q]), ch);
            }
            yr[t0 + q] = __fadd_rn(__fadd_rn(f[0], f[1]), __fadd_rn(f[2], f[3]));
        }
    }
}

// ---------------- psp (plain input) --------------------------------------------
__global__ void psp_kernel(const float* __restrict__ x, float* __restrict__ y) {
    __shared__ __align__(16) float sxp[404];   // 99 zeros + 300 row + pad
    __shared__ __align__(16) float sK[104];
    long long r = blockIdx.x;
    const float* xr = x + r * TT;
    int tid = threadIdx.x;
    for (int i = tid; i < 99; i += blockDim.x) sxp[i] = 0.f;
    for (int i = tid; i < TT; i += blockDim.x) sxp[99 + i] = xr[i];
    for (int i = tid; i < 104; i += blockDim.x) sK[i] = g_K[i];
    __syncthreads();
    psp_compute(sxp, sK, tid, y + r * TT);
}

// ---------------- psp with fused per-channel fractional delay ------------------
// sxp[99+t] = (1-fr)*x[t-tfi] + fr*x[t-tfi-1]  (exact same non-fma ops as the
// standalone delay kernel, then the identical psp compute) -> bit-exact fusion.
__global__ void psp_delay_kernel(const float* __restrict__ X, float* __restrict__ Y,
                                 const float* __restrict__ D, int C, int Wd) {
    __shared__ __align__(16) float sxp[404];
    __shared__ __align__(16) float sK[104];
    long long r = blockIdx.x;
    int c = (int)((r / Wd) % C);
    float d = D[c];
    float tf = floorf(d);
    int tfi = (int)tf;
    float fr = __fsub_rn(d, tf);
    float omfr = __fsub_rn(1.0f, fr);
    const float* xr = X + r * TT;
    int tid = threadIdx.x;
    for (int i = tid; i < 99; i += blockDim.x) sxp[i] = 0.f;
    for (int t = tid; t < TT; t += blockDim.x) {
        int i0 = t - tfi, i1 = i0 - 1;
        float g0 = (i0 >= 0) ? xr[i0] : 0.f;
        float g1 = (i1 >= 0) ? xr[i1] : 0.f;
        sxp[99 + t] = __fadd_rn(__fmul_rn(omfr, g0), __fmul_rn(fr, g1));
    }
    for (int i = tid; i < 104; i += blockDim.x) sK[i] = g_K[i];
    __syncthreads();
    psp_compute(sxp, sK, tid, Y + r * TT);
}

// ---------------- conv (1 x 3, stride 2 along W) + spike -----------------------
template <int CIN, int COUT, int PAD>
__global__ void conv_spike_kernel(const float* __restrict__ X,
                                  const float* __restrict__ Wt,
                                  float* __restrict__ Y,
                                  int Win, int Wout) {
    extern __shared__ float sm[];
    const int CK = CIN * 3;
    float* sW = sm;             // COUT*CK
    float* sX = sm + COUT * CK; // CK*TT
    int wo = blockIdx.x, n = blockIdx.y;
    int tid = threadIdx.x; int NT = blockDim.x;

    for (int i = tid; i < COUT * CK; i += NT) sW[i] = Wt[i];
    for (int i = tid; i < CK * TT; i += NT) {
        int idx = i / TT, t = i - idx * TT;
        int ci = idx / 3, kw = idx - ci * 3;
        int wi = wo * 2 - PAD + kw;
        float v = 0.f;
        if (wi >= 0 && wi < Win)
            v = X[((long long)(n * CIN + ci) * Win + wi) * TT + t];
        sX[i] = v;
    }
    __syncthreads();

    const int TCOG = COUT / 4;
    const int TASKS = TCOG * 75;    // 75 t-groups of 4
    for (int task = tid; task < TASKS; task += NT) {
        int cog = task / 75, tg = task - cog * 75;
        int co0 = cog * 4, t0 = tg * 4;
        float acc[4][4];
        #pragma unroll
        for (int j = 0; j < 4; ++j)
            acc[j][0] = acc[j][1] = acc[j][2] = acc[j][3] = 0.f;
        for (int ck = 0; ck < CK; ++ck) {
            float4 xv = *(const float4*)&sX[ck * TT + t0];
            #pragma unroll
            for (int j = 0; j < 4; ++j) {
                float wv = sW[(co0 + j) * CK + ck];
                acc[j][0] = fmaf(wv, xv.x, acc[j][0]);
                acc[j][1] = fmaf(wv, xv.y, acc[j][1]);
                acc[j][2] = fmaf(wv, xv.z, acc[j][2]);
                acc[j][3] = fmaf(wv, xv.w, acc[j][3]);
            }
        }
        #pragma unroll
        for (int j = 0; j < 4; ++j) {
            float* yp = Y + ((long long)(n * COUT + co0 + j) * Wout + wo) * TT + t0;
            #pragma unroll
            for (int q = 0; q < 4; ++q)
                yp[q] = (acc[j][q] >= 1.0f) ? 1.0f : 0.0f;
        }
    }
}

// ---------------- dense1 (512 x 2816) per time step + spike --------------------
__global__ void dense1_spike_kernel(const float* __restrict__ A,
                                    const float* __restrict__ Wt,
                                    float* __restrict__ Y) {
    __shared__ float sA[32 * 64];
    __shared__ float sW[64 * 33];
    int tb = blockIdx.x * 64, ob = blockIdx.y * 64, n = blockIdx.z;
    int tid = threadIdx.x;                 // 256
    int to = tid & 15, tg = tid >> 4;
    int o0 = to * 4, t0 = tg * 4;
    float acc[4][4];
    #pragma unroll
    for (int j = 0; j < 4; ++j)
        acc[j][0] = acc[j][1] = acc[j][2] = acc[j][3] = 0.f;
    const float* An = A + (long long)n * 2816 * TT;

    for (int k0 = 0; k0 < 2816; k0 += 32) {
        for (int i = tid; i < 2048; i += 256) {
            int k = i >> 6, t = i & 63;
            int tgl = tb + t;
            sA[k * 64 + t] = (tgl < TT) ? An[(long long)(k0 + k) * TT + tgl] : 0.f;
        }
        for (int i = tid; i < 2048; i += 256) {
            int o = i >> 5, k = i & 31;
            sW[o * 33 + k] = Wt[(long long)(ob + o) * 2816 + k0 + k];
        }
        __syncthreads();
        #pragma unroll 8
        for (int k = 0; k < 32; ++k) {
            float4 av = *(const float4*)&sA[k * 64 + t0];
            float w0 = sW[(o0 + 0) * 33 + k];
            float w1 = sW[(o0 + 1) * 33 + k];
            float w2 = sW[(o0 + 2) * 33 + k];
            float w3 = sW[(o0 + 3) * 33 + k];
            acc[0][0] = fmaf(w0, av.x, acc[0][0]); acc[0][1] = fmaf(w0, av.y, acc[0][1]);
            acc[0][2] = fmaf(w0, av.z, acc[0][2]); acc[0][3] = fmaf(w0, av.w, acc[0][3]);
            acc[1][0] = fmaf(w1, av.x, acc[1][0]); acc[1][1] = fmaf(w1, av.y, acc[1][1]);
            acc[1][2] = fmaf(w1, av.z, acc[1][2]); acc[1][3] = fmaf(w1, av.w, acc[1][3]);
            acc[2][0] = fmaf(w2, av.x, acc[2][0]); acc[2][1] = fmaf(w2, av.y, acc[2][1]);
            acc[2][2] = fmaf(w2, av.z, acc[2][2]); acc[2][3] = fmaf(w2, av.w, acc[2][3]);
            acc[3][0] = fmaf(w3, av.x, acc[3][0]); acc[3][1] = fmaf(w3, av.y, acc[3][1]);
            acc[3][2] = fmaf(w3, av.z, acc[3][2]); acc[3][3] = fmaf(w3, av.w, acc[3][3]);
        }
        __syncthreads();
    }
    #pragma unroll
    for (int j = 0; j < 4; ++j) {
        #pragma unroll
        for (int q = 0; q < 4; ++q) {
            int t = tb + t0 + q;
            if (t < TT)
                Y[((long long)(n * 512 + ob + o0 + j)) * TT + t] =
                    (acc[j][q] >= 1.0f) ? 1.0f : 0.0f;
        }
    }
}

// ---------------- dense2 (35 x 512) + spike -> d_out ---------------------------
__global__ void dense2_spike_kernel(const float* __restrict__ A,
                                    const float* __restrict__ Wt,
                                    float* __restrict__ Y) {
    int o = blockIdx.x, n = blockIdx.y;
    __shared__ float sw[512];
    for (int i = threadIdx.x; i < 512; i += blockDim.x) sw[i] = Wt[o * 512 + i];
    __syncthreads();
    const float* An = A + (long long)n * 512 * TT;
    for (int t = threadIdx.x; t < TT; t += blockDim.x) {
        float acc = 0.f;
        for (int f = 0; f < 512; ++f)
            acc = fmaf(sw[f], An[(long long)f * TT + t], acc);
        Y[((long long)(n * 35 + o)) * TT + t] = (acc >= 1.0f) ? 1.0f : 0.0f;
    }
}

// ---------------- launch sequence ----------------------------------------------
extern "C" void kernel_launch(void* const* d_in, const int* in_sizes, int n_in,
                              void* d_out, int out_size) {
    (void)in_sizes; (void)n_in; (void)out_size;
    const float* spike = (const float*)d_in[0];
    const float* W1 = (const float*)d_in[1];
    const float* W2 = (const float*)d_in[2];
    const float* W3 = (const float*)d_in[3];
    const float* W4 = (const float*)d_in[4];
    const float* Wf1 = (const float*)d_in[5];
    const float* Wf2 = (const float*)d_in[6];
    const float* d1 = (const float*)d_in[7];
    const float* d2 = (const float*)d_in[8];
    const float* d3 = (const float*)d_in[9];
    const float* d4 = (const float*)d_in[10];
    const float* d5 = (const float*)d_in[11];

    float *b0, *b1;
    cudaGetSymbolAddress((void**)&b0, g_buf0);
    cudaGetSymbolAddress((void**)&b1, g_buf1);

    cudaFuncSetAttribute(conv_spike_kernel<16, 32, 1>,
                         cudaFuncAttributeMaxDynamicSharedMemorySize, (1536 + 48 * TT) * 4);
    cudaFuncSetAttribute(conv_spike_kernel<32, 64, 1>,
                         cudaFuncAttributeMaxDynamicSharedMemorySize, (6144 + 96 * TT) * 4);

    init_kernel<<<1, 128>>>();

    // layer 1: (32,1,691) -> (32,8,345)
    psp_kernel<<<32 * 691, 128>>>(spike, b0);
    conv_spike_kernel<1, 8, 0><<<dim3(345, 32), 128, (24 + 3 * TT) * 4>>>(b0, W1, b1, 691, 345);

    // layer 2: delay(d1) fused into psp
    psp_delay_kernel<<<32 * 8 * 345, 128>>>(b1, b0, d1, 8, 345);
    conv_spike_kernel<8, 16, 1><<<dim3(173, 32), 128, (384 + 24 * TT) * 4>>>(b0, W2, b1, 345, 173);

    // layer 3
    psp_delay_kernel<<<32 * 16 * 173, 128>>>(b1, b0, d2, 16, 173);
    conv_spike_kernel<16, 32, 1><<<dim3(87, 32), 256, (1536 + 48 * TT) * 4>>>(b0, W3, b1, 173, 87);

    // layer 4
    psp_delay_kernel<<<32 * 32 * 87, 128>>>(b1, b0, d3, 32, 87);
    conv_spike_kernel<32, 64, 1><<<dim3(44, 32), 256, (6144 + 96 * TT) * 4>>>(b0, W4, b1, 87, 44);

    // dense 1 (features f = c*44+w = 2816)
    psp_delay_kernel<<<32 * 64 * 44, 128>>>(b1, b0, d4, 64, 44);
    dense1_spike_kernel<<<dim3(5, 8, 32), 256>>>(b0, Wf1, b1);

    // dense 2 -> output (32,35,300)
    psp_delay_kernel<<<32 * 512, 128>>>(b1, b0, d5, 512, 1);
    dense2_spike_kernel<<<dim3(35, 32), 128>>>(b0, Wf2, (float*)d_out);
}